// round 5
// baseline (speedup 1.0000x reference)
#include <cuda_runtime.h>

#define N_MAX 128
#define BB 4
#define BH 136
#define BW 200
#define OUT 56
#define CO 14
#define IMG_H 544
#define IMG_W 800
#define BF_STRIDE (1 + 4 + BB * CO * CO) /* 789 */

// Per-ROI paste region: 384 x 232 px (max box 320 x 217.6 + slack).
#define RGN_H 232
#define XT 3    /* x tiles of 128 px */
#define YT 29   /* y tiles of 8 rows */

// Device scratch (no allocs).
__device__ float g_masks[N_MAX * OUT * OUT];            // 56x56 blended masks
__device__ float g_exp[N_MAX * RGN_H * OUT];            // y-expanded rows (6.6 MB)

// ---------------------------------------------------------------------------
// Kernel 1: fused roi_align + coeff bilinear upsample + softmax + sigmoid.
// ---------------------------------------------------------------------------
__global__ void masks_kernel(const float* __restrict__ bases,
                             const float* __restrict__ bf) {
    int n = blockIdx.x;
    int chunk = blockIdx.y;                  // 0..6, 8 rows each
    const float* row = bf + (size_t)n * BF_STRIDE;

    __shared__ float s_top[BB * CO * CO];
    for (int i = threadIdx.x; i < BB * CO * CO; i += blockDim.x)
        s_top[i] = row[5 + i];
    __syncthreads();

    int bidx = (int)row[0];
    float bx0 = row[1], by0 = row[2], bx1 = row[3], by1 = row[4];
    const float* feat = bases + (size_t)bidx * (BB * BH * BW);

    float sx0 = bx0 * 0.25f - 0.5f;
    float sy0 = by0 * 0.25f - 0.5f;
    float sx1 = bx1 * 0.25f - 0.5f;
    float sy1 = by1 * 0.25f - 0.5f;
    float bwd = (sx1 - sx0) * (1.0f / OUT);
    float bhd = (sy1 - sy0) * (1.0f / OUT);

    int p0 = chunk * 448;
    for (int t = threadIdx.x; t < 448; t += blockDim.x) {
        int p = p0 + t;
        int i = p / OUT;
        int j = p - i * OUT;

        float ys = sy0 + (i + 0.5f) * bhd;
        float xs = sx0 + (j + 0.5f) * bwd;
        bool valid = (ys >= -1.0f) && (ys <= (float)BH) &&
                     (xs >= -1.0f) && (xs <= (float)BW);
        float yc = fminf(fmaxf(ys, 0.0f), (float)(BH - 1));
        float xc = fminf(fmaxf(xs, 0.0f), (float)(BW - 1));
        int yl = min((int)yc, BH - 2);
        int xl = min((int)xc, BW - 2);
        float ly = yc - (float)yl, hy = 1.0f - ly;
        float lx = xc - (float)xl, hx = 1.0f - lx;

        float cy = fminf(fmaxf((i + 0.5f) * 0.25f - 0.5f, 0.0f), (float)(CO - 1));
        float cx = fminf(fmaxf((j + 0.5f) * 0.25f - 0.5f, 0.0f), (float)(CO - 1));
        int cyl = min((int)cy, CO - 2);
        int cxl = min((int)cx, CO - 2);
        float ty = cy - (float)cyl, sy = 1.0f - ty;
        float tx = cx - (float)cxl, sx = 1.0f - tx;

        float roi[BB], cf[BB];
#pragma unroll
        for (int b = 0; b < BB; b++) {
            const float* f = feat + b * BH * BW + yl * BW + xl;
            float fll = __ldg(f);
            float flh = __ldg(f + 1);
            float fhl = __ldg(f + BW);
            float fhh = __ldg(f + BW + 1);
            float v = hy * (hx * fll + lx * flh) + ly * (hx * fhl + lx * fhh);
            roi[b] = valid ? v : 0.0f;

            const float* tp = s_top + b * CO * CO + cyl * CO + cxl;
            cf[b] = sy * (sx * tp[0] + tx * tp[1]) + ty * (sx * tp[CO] + tx * tp[CO + 1]);
        }

        float m = fmaxf(fmaxf(cf[0], cf[1]), fmaxf(cf[2], cf[3]));
        float e0 = __expf(cf[0] - m), e1 = __expf(cf[1] - m);
        float e2 = __expf(cf[2] - m), e3 = __expf(cf[3] - m);
        float inv = 1.0f / (e0 + e1 + e2 + e3);
        float dot = (roi[0] * e0 + roi[1] * e1 + roi[2] * e2 + roi[3] * e3) * inv;
        g_masks[n * OUT * OUT + p] = 1.0f / (1.0f + __expf(-dot));
    }
}

// ---------------------------------------------------------------------------
// Kernel 2: y-expansion. For each region row y' of each ROI, interpolate the
// two mask rows into e[n][y'][0..55]. Rows outside (-1, 56) in fy are zeroed.
// Grid (n_roi, YT), block (56, 8).
// ---------------------------------------------------------------------------
__global__ void expand_kernel(const float* __restrict__ bf) {
    int n = blockIdx.x;
    const float* row = bf + (size_t)n * BF_STRIDE;
    float y0 = __ldg(row + 2), y1 = __ldg(row + 4);
    int ys = max(0, (int)floorf(y0) - 4);

    int yp = blockIdx.y * 8 + threadIdx.y;   // 0..231
    int c = threadIdx.x;                     // 0..55
    int y = ys + yp;

    float inv_h = __fdividef((float)OUT, y1 - y0);
    float fy = ((float)y + 0.5f - y0) * inv_h - 0.5f;

    float val = 0.0f;
    if (fy > -1.0f && fy < (float)OUT) {
        float fmy = floorf(fy);
        int r0i = (int)fmy;
        float wy1 = fy - fmy, wy0 = 1.0f - wy1;
        int r0 = max(r0i, 0);
        int r1 = min(r0i + 1, OUT - 1);
        if (r0i < 0) wy0 = 0.0f;
        if (r0i + 1 > OUT - 1) wy1 = 0.0f;
        const float* M = g_masks + n * OUT * OUT;
        val = wy0 * __ldg(M + r0 * OUT + c) + wy1 * __ldg(M + r1 * OUT + c);
    }
    g_exp[(n * RGN_H + yp) * OUT + c] = val;
}

// ---------------------------------------------------------------------------
// Kernel 3: paste. x-interp only, reading the expanded row (L1-hot).
// One float4 store (4 px) per thread. Grid (XT, YT, n_roi), block (32, 8).
// ---------------------------------------------------------------------------
__global__ void __launch_bounds__(256)
paste_box_kernel(const float* __restrict__ bf, float* __restrict__ out) {
    int n = blockIdx.z;
    const float* row = bf + (size_t)n * BF_STRIDE;
    float x0 = __ldg(row + 1), y0 = __ldg(row + 2);
    float x1 = __ldg(row + 3);

    int xs = max(0, ((int)floorf(x0) - 4)) & ~3;
    int ys = max(0, (int)floorf(y0) - 4);

    int yp = blockIdx.y * 8 + threadIdx.y;   // region-row index 0..231
    int y = ys + yp;
    if (y >= IMG_H) return;

    int x = xs + (blockIdx.x * 32 + threadIdx.x) * 4;
    if (x + 3 >= IMG_W) return;

    float inv_w = __fdividef((float)OUT, x1 - x0);
    float fxs = ((float)x + 0.5f - x0) * inv_w - 0.5f;
    if (fxs + 3.0f * inv_w <= -1.0f || fxs >= (float)OUT) return;

    const float* e = g_exp + (n * RGN_H + yp) * OUT;

    float v[4];
#pragma unroll
    for (int k = 0; k < 4; k++) {
        float fx = fxs + (float)k * inv_w;
        bool valid = (fx > -1.0f) && (fx < (float)OUT);
        float fmx = floorf(fx);
        int c0i = (int)fmx;
        float wx1 = fx - fmx, wx0 = 1.0f - wx1;
        int c0 = min(max(c0i, 0), OUT - 1);
        int c1 = min(c0i + 1, OUT - 1);
        if (c0i < 0) wx0 = 0.0f;
        if (c0i + 1 > OUT - 1) wx1 = 0.0f;
        float val = wx0 * __ldg(e + c0) + wx1 * __ldg(e + c1);
        v[k] = valid ? val : 0.0f;
    }

    float4* dst = (float4*)(out + (size_t)n * (IMG_H * IMG_W) + y * IMG_W + x);
    *dst = make_float4(v[0], v[1], v[2], v[3]);
}

// ---------------------------------------------------------------------------
// Static side stream + fork/join events (created once at module init; streams
// and events are not device-memory allocations).
// ---------------------------------------------------------------------------
struct HxRes {
    cudaStream_t side;
    cudaEvent_t fork, join;
    HxRes() {
        cudaStreamCreateWithFlags(&side, cudaStreamNonBlocking);
        cudaEventCreateWithFlags(&fork, cudaEventDisableTiming);
        cudaEventCreateWithFlags(&join, cudaEventDisableTiming);
    }
};
static HxRes hx;

extern "C" void kernel_launch(void* const* d_in, const int* in_sizes, int n_in,
                              void* d_out, int out_size) {
    const float* bases = (const float*)d_in[0];
    const float* bf = (const float*)d_in[1];
    int n_roi = in_sizes[1] / BF_STRIDE;
    if (n_roi > N_MAX) n_roi = N_MAX;

    // Fork: masks + expand on the side stream, overlapped with the memset.
    cudaEventRecord(hx.fork, 0);
    cudaStreamWaitEvent(hx.side, hx.fork, 0);

    dim3 mgrid(n_roi, 7);
    masks_kernel<<<mgrid, 256, 0, hx.side>>>(bases, bf);

    dim3 eblock(56, 8);
    dim3 egrid(n_roi, YT);
    expand_kernel<<<egrid, eblock, 0, hx.side>>>(bf);

    cudaEventRecord(hx.join, hx.side);

    // Bulk zero-fill on the main stream (runs concurrently with the above).
    cudaMemsetAsync(d_out, 0, (size_t)out_size * sizeof(float));

    // Join, then paste.
    cudaStreamWaitEvent(0, hx.join, 0);
    dim3 pblock(32, 8);
    dim3 pgrid(XT, YT, n_roi);
    paste_box_kernel<<<pgrid, pblock>>>(bf, (float*)d_out);
}

// round 6
// speedup vs baseline: 1.0159x; 1.0159x over previous
#include <cuda_runtime.h>

#define N_MAX 128
#define BB 4
#define BH 136
#define BW 200
#define OUT 56
#define CO 14
#define IMG_H 544
#define IMG_W 800
#define BF_STRIDE (1 + 4 + BB * CO * CO) /* 789 */

// Per-ROI paste region: 384 x 232 px (max box 320 x 217.6 + slack).
#define XT 3    /* x tiles of 128 px */
#define YT 29   /* y tiles of 8 rows */

// Scratch for the blended 56x56 masks (1.25 MB) — device global, no allocs.
__device__ float g_masks[N_MAX * OUT * OUT];

// ---------------------------------------------------------------------------
// Kernel 1: fused roi_align + coeff bilinear upsample + softmax + sigmoid.
// Grid (n_roi, 7): each block handles 8 mask rows (448 px) of one ROI.
// ---------------------------------------------------------------------------
__global__ void masks_kernel(const float* __restrict__ bases,
                             const float* __restrict__ bf) {
    int n = blockIdx.x;
    int chunk = blockIdx.y;                  // 0..6, 8 rows each
    const float* row = bf + (size_t)n * BF_STRIDE;

    __shared__ float s_top[BB * CO * CO];
    for (int i = threadIdx.x; i < BB * CO * CO; i += blockDim.x)
        s_top[i] = row[5 + i];
    __syncthreads();

    int bidx = (int)row[0];
    float bx0 = row[1], by0 = row[2], bx1 = row[3], by1 = row[4];
    const float* feat = bases + (size_t)bidx * (BB * BH * BW);

    float sx0 = bx0 * 0.25f - 0.5f;
    float sy0 = by0 * 0.25f - 0.5f;
    float sx1 = bx1 * 0.25f - 0.5f;
    float sy1 = by1 * 0.25f - 0.5f;
    float bwd = (sx1 - sx0) * (1.0f / OUT);
    float bhd = (sy1 - sy0) * (1.0f / OUT);

    int p0 = chunk * 448;
    for (int t = threadIdx.x; t < 448; t += blockDim.x) {
        int p = p0 + t;
        int i = p / OUT;
        int j = p - i * OUT;

        float ys = sy0 + (i + 0.5f) * bhd;
        float xs = sx0 + (j + 0.5f) * bwd;
        bool valid = (ys >= -1.0f) && (ys <= (float)BH) &&
                     (xs >= -1.0f) && (xs <= (float)BW);
        float yc = fminf(fmaxf(ys, 0.0f), (float)(BH - 1));
        float xc = fminf(fmaxf(xs, 0.0f), (float)(BW - 1));
        int yl = min((int)yc, BH - 2);
        int xl = min((int)xc, BW - 2);
        float ly = yc - (float)yl, hy = 1.0f - ly;
        float lx = xc - (float)xl, hx = 1.0f - lx;

        float cy = fminf(fmaxf((i + 0.5f) * 0.25f - 0.5f, 0.0f), (float)(CO - 1));
        float cx = fminf(fmaxf((j + 0.5f) * 0.25f - 0.5f, 0.0f), (float)(CO - 1));
        int cyl = min((int)cy, CO - 2);
        int cxl = min((int)cx, CO - 2);
        float ty = cy - (float)cyl, sy = 1.0f - ty;
        float tx = cx - (float)cxl, sx = 1.0f - tx;

        float roi[BB], cf[BB];
#pragma unroll
        for (int b = 0; b < BB; b++) {
            const float* f = feat + b * BH * BW + yl * BW + xl;
            float fll = __ldg(f);
            float flh = __ldg(f + 1);
            float fhl = __ldg(f + BW);
            float fhh = __ldg(f + BW + 1);
            float v = hy * (hx * fll + lx * flh) + ly * (hx * fhl + lx * fhh);
            roi[b] = valid ? v : 0.0f;

            const float* tp = s_top + b * CO * CO + cyl * CO + cxl;
            cf[b] = sy * (sx * tp[0] + tx * tp[1]) + ty * (sx * tp[CO] + tx * tp[CO + 1]);
        }

        float m = fmaxf(fmaxf(cf[0], cf[1]), fmaxf(cf[2], cf[3]));
        float e0 = __expf(cf[0] - m), e1 = __expf(cf[1] - m);
        float e2 = __expf(cf[2] - m), e3 = __expf(cf[3] - m);
        float inv = 1.0f / (e0 + e1 + e2 + e3);
        float dot = (roi[0] * e0 + roi[1] * e1 + roi[2] * e2 + roi[3] * e3) * inv;
        g_masks[n * OUT * OUT + p] = 1.0f / (1.0f + __expf(-dot));
    }
}

// ---------------------------------------------------------------------------
// Kernel 2: paste with in-block y-expansion. Each block covers a 128x8 px
// tile of one ROI's region. Step 1: 256 threads compute the 8 expanded rows
// (8x56 y-interp values) into smem. Step 2: x-interp from smem, one float4
// store (4 px) per thread. Out-of-box groups / invalid rows skip the store
// (memset already zeroed). Grid (XT, YT, n_roi), block (32, 8).
// ---------------------------------------------------------------------------
#define EPITCH 60   /* 56 + pad to dodge bank conflicts */

__global__ void __launch_bounds__(256)
paste_box_kernel(const float* __restrict__ bf, float* __restrict__ out) {
    __shared__ float s_e[8 * EPITCH];

    int n = blockIdx.z;
    const float* row = bf + (size_t)n * BF_STRIDE;
    float x0 = __ldg(row + 1), y0 = __ldg(row + 2);
    float x1 = __ldg(row + 3), y1 = __ldg(row + 4);

    int xs = max(0, ((int)floorf(x0) - 4)) & ~3;
    int ys = max(0, (int)floorf(y0) - 4);

    float inv_h = __fdividef((float)OUT, y1 - y0);
    int yp0 = blockIdx.y * 8;                 // first region row of this tile

    int tid = threadIdx.y * 32 + threadIdx.x;

    // ---- Step 1: y-expansion into smem (448 values, <=2 per thread) ----
#pragma unroll
    for (int t = tid; t < 8 * OUT; t += 256) {
        int r = t / OUT;                      // row within tile 0..7
        int c = t - r * OUT;                  // mask column 0..55
        int y = ys + yp0 + r;
        float fy = ((float)y + 0.5f - y0) * inv_h - 0.5f;
        float val = 0.0f;
        if (fy > -1.0f && fy < (float)OUT) {
            float fmy = floorf(fy);
            int r0i = (int)fmy;
            float wy1 = fy - fmy, wy0 = 1.0f - wy1;
            int r0 = max(r0i, 0);
            int r1 = min(r0i + 1, OUT - 1);
            if (r0i < 0) wy0 = 0.0f;
            if (r0i + 1 > OUT - 1) wy1 = 0.0f;
            const float* M = g_masks + n * OUT * OUT;
            val = wy0 * __ldg(M + r0 * OUT + c) + wy1 * __ldg(M + r1 * OUT + c);
        }
        s_e[r * EPITCH + c] = val;
    }
    __syncthreads();

    // ---- Step 2: x-interp + store ----
    int y = ys + yp0 + threadIdx.y;
    if (y >= IMG_H) return;

    // Skip stores on rows fully outside the box in y (memset covers them).
    float fy = ((float)y + 0.5f - y0) * inv_h - 0.5f;
    if (fy <= -1.0f || fy >= (float)OUT) return;

    int x = xs + (blockIdx.x * 32 + threadIdx.x) * 4;
    if (x + 3 >= IMG_W) return;

    float inv_w = __fdividef((float)OUT, x1 - x0);
    float fxs = ((float)x + 0.5f - x0) * inv_w - 0.5f;
    if (fxs + 3.0f * inv_w <= -1.0f || fxs >= (float)OUT) return;

    const float* e = s_e + threadIdx.y * EPITCH;

    float v[4];
#pragma unroll
    for (int k = 0; k < 4; k++) {
        float fx = fxs + (float)k * inv_w;
        bool valid = (fx > -1.0f) && (fx < (float)OUT);
        float fmx = floorf(fx);
        int c0i = (int)fmx;
        float wx1 = fx - fmx, wx0 = 1.0f - wx1;
        int c0 = min(max(c0i, 0), OUT - 1);
        int c1 = min(c0i + 1, OUT - 1);
        if (c0i < 0) wx0 = 0.0f;
        if (c0i + 1 > OUT - 1) wx1 = 0.0f;
        float val = wx0 * e[c0] + wx1 * e[c1];
        v[k] = valid ? val : 0.0f;
    }

    float4* dst = (float4*)(out + (size_t)n * (IMG_H * IMG_W) + y * IMG_W + x);
    *dst = make_float4(v[0], v[1], v[2], v[3]);
}

extern "C" void kernel_launch(void* const* d_in, const int* in_sizes, int n_in,
                              void* d_out, int out_size) {
    const float* bases = (const float*)d_in[0];
    const float* bf = (const float*)d_in[1];
    int n_roi = in_sizes[1] / BF_STRIDE;
    if (n_roi > N_MAX) n_roi = N_MAX;

    // Bulk zero-fill at memset-node bandwidth.
    cudaMemsetAsync(d_out, 0, (size_t)out_size * sizeof(float));

    dim3 mgrid(n_roi, 7);
    masks_kernel<<<mgrid, 256>>>(bases, bf);

    dim3 pblock(32, 8);
    dim3 pgrid(XT, YT, n_roi);
    paste_box_kernel<<<pgrid, pblock>>>(bf, (float*)d_out);
}

// round 7
// speedup vs baseline: 1.0607x; 1.0442x over previous
#include <cuda_runtime.h>

#define N_MAX 128
#define BB 4
#define BH 136
#define BW 200
#define OUT 56
#define CO 14
#define IMG_H 544
#define IMG_W 800
#define BF_STRIDE (1 + 4 + BB * CO * CO) /* 789 */

#define XT 3    /* x tiles of 128 px (384 >= max box w 320 + slack) */
#define YT 29   /* y tiles of 8 rows (232 >= max box h 217.6 + slack) */

// Padded mask storage: per ROI 58 rows x 64 pitch, data at [1..56][1..56],
// zero border at row/col 0 and 57; cols 58..63 never written (stay 0 from
// .bss zero-init). ~1.9 MB.
#define MROWS 58
#define MPITCH 64
__device__ float g_mpad[N_MAX * MROWS * MPITCH];

// ---------------------------------------------------------------------------
// Kernel 1: fused roi_align + coeff bilinear upsample + softmax + sigmoid,
// writing into the padded layout. Chunk 0 also zeroes the border.
// Grid (n_roi, 7), block 256.
// ---------------------------------------------------------------------------
__global__ void masks_kernel(const float* __restrict__ bases,
                             const float* __restrict__ bf) {
    int n = blockIdx.x;
    int chunk = blockIdx.y;                  // 0..6, 8 mask rows each
    const float* row = bf + (size_t)n * BF_STRIDE;
    float* mp = g_mpad + (size_t)n * MROWS * MPITCH;

    // Zero border (rows 0 & 57 full width, cols 0 & 57 of rows 1..56).
    if (chunk == 0) {
        int t = threadIdx.x;
        if (t < MROWS) {                      // 58 threads: row 0 and row 57
            mp[t] = 0.0f;                     // row 0, col t
            mp[57 * MPITCH + t] = 0.0f;       // row 57, col t
        } else if (t < MROWS + 112) {         // 112 threads: side cols
            int k = t - MROWS;                // 0..111
            int r = 1 + (k >> 1);             // 1..56
            int c = (k & 1) ? 57 : 0;
            mp[r * MPITCH + c] = 0.0f;
        }
    }

    __shared__ float s_top[BB * CO * CO];
    for (int i = threadIdx.x; i < BB * CO * CO; i += blockDim.x)
        s_top[i] = row[5 + i];
    __syncthreads();

    int bidx = (int)row[0];
    float bx0 = row[1], by0 = row[2], bx1 = row[3], by1 = row[4];
    const float* feat = bases + (size_t)bidx * (BB * BH * BW);

    float sx0 = bx0 * 0.25f - 0.5f;
    float sy0 = by0 * 0.25f - 0.5f;
    float sx1 = bx1 * 0.25f - 0.5f;
    float sy1 = by1 * 0.25f - 0.5f;
    float bwd = (sx1 - sx0) * (1.0f / OUT);
    float bhd = (sy1 - sy0) * (1.0f / OUT);

    int p0 = chunk * 448;
    for (int t = threadIdx.x; t < 448; t += blockDim.x) {
        int p = p0 + t;
        int i = p / OUT;
        int j = p - i * OUT;

        float ys = sy0 + (i + 0.5f) * bhd;
        float xs = sx0 + (j + 0.5f) * bwd;
        bool valid = (ys >= -1.0f) && (ys <= (float)BH) &&
                     (xs >= -1.0f) && (xs <= (float)BW);
        float yc = fminf(fmaxf(ys, 0.0f), (float)(BH - 1));
        float xc = fminf(fmaxf(xs, 0.0f), (float)(BW - 1));
        int yl = min((int)yc, BH - 2);
        int xl = min((int)xc, BW - 2);
        float ly = yc - (float)yl, hy = 1.0f - ly;
        float lx = xc - (float)xl, hx = 1.0f - lx;

        float cy = fminf(fmaxf((i + 0.5f) * 0.25f - 0.5f, 0.0f), (float)(CO - 1));
        float cx = fminf(fmaxf((j + 0.5f) * 0.25f - 0.5f, 0.0f), (float)(CO - 1));
        int cyl = min((int)cy, CO - 2);
        int cxl = min((int)cx, CO - 2);
        float ty = cy - (float)cyl, sy = 1.0f - ty;
        float tx = cx - (float)cxl, sx = 1.0f - tx;

        float roi[BB], cf[BB];
#pragma unroll
        for (int b = 0; b < BB; b++) {
            const float* f = feat + b * BH * BW + yl * BW + xl;
            float fll = __ldg(f);
            float flh = __ldg(f + 1);
            float fhl = __ldg(f + BW);
            float fhh = __ldg(f + BW + 1);
            float v = hy * (hx * fll + lx * flh) + ly * (hx * fhl + lx * fhh);
            roi[b] = valid ? v : 0.0f;

            const float* tp = s_top + b * CO * CO + cyl * CO + cxl;
            cf[b] = sy * (sx * tp[0] + tx * tp[1]) + ty * (sx * tp[CO] + tx * tp[CO + 1]);
        }

        float m = fmaxf(fmaxf(cf[0], cf[1]), fmaxf(cf[2], cf[3]));
        float e0 = __expf(cf[0] - m), e1 = __expf(cf[1] - m);
        float e2 = __expf(cf[2] - m), e3 = __expf(cf[3] - m);
        float inv = 1.0f / (e0 + e1 + e2 + e3);
        float dot = (roi[0] * e0 + roi[1] * e1 + roi[2] * e2 + roi[3] * e3) * inv;
        // padded store: row i+1, col j+1
        mp[(i + 1) * MPITCH + (j + 1)] = 1.0f / (1.0f + __expf(-dot));
    }
}

// ---------------------------------------------------------------------------
// Kernel 2: paste from the padded mask — no index clamps / weight zeroing on
// the interpolation taps. One float4 store (4 px) per thread; out-of-box work
// skips the store (memset covers zeros). Grid (XT, YT, n_roi), block (32, 8).
// ---------------------------------------------------------------------------
__global__ void __launch_bounds__(256)
paste_box_kernel(const float* __restrict__ bf, float* __restrict__ out) {
    int n = blockIdx.z;
    const float* row = bf + (size_t)n * BF_STRIDE;
    float x0 = __ldg(row + 1), y0 = __ldg(row + 2);
    float x1 = __ldg(row + 3), y1 = __ldg(row + 4);

    int xs = max(0, ((int)floorf(x0) - 4)) & ~3;
    int ys = max(0, (int)floorf(y0) - 4);

    int y = ys + blockIdx.y * 8 + threadIdx.y;
    if (y >= IMG_H) return;

    float inv_h = __fdividef((float)OUT, y1 - y0);
    float fy = ((float)y + 0.5f - y0) * inv_h - 0.5f;
    if (fy <= -1.0f || fy >= (float)OUT) return;   // memset covers these rows

    int x = xs + (blockIdx.x * 32 + threadIdx.x) * 4;
    if (x + 3 >= IMG_W) return;

    float inv_w = __fdividef((float)OUT, x1 - x0);
    float fxs = ((float)x + 0.5f - x0) * inv_w - 0.5f;
    if (fxs + 3.0f * inv_w <= -1.0f || fxs >= (float)OUT) return;

    // y taps: fy in (-1,56) => r0i in [-1,55] => padded rows r0i+1, r0i+2.
    float fmy = floorf(fy);
    float wy1 = fy - fmy, wy0 = 1.0f - wy1;
    int r0 = (int)fmy + 1;
    const float* M0 = g_mpad + ((size_t)n * MROWS + r0) * MPITCH;
    const float* M1 = M0 + MPITCH;

    float v[4];
#pragma unroll
    for (int k = 0; k < 4; k++) {
        float fx = fxs + (float)k * inv_w;
        bool p = (fx > -1.0f) && (fx < (float)OUT);
        float fmx = floorf(fx);
        float wx1 = fx - fmx, wx0 = 1.0f - wx1;
        int c = max((int)fmx, -1) + 1;        // 0..62, pitch-64 row reads 0s
        float a = wx0 * __ldg(M0 + c) + wx1 * __ldg(M0 + c + 1);
        float b = wx0 * __ldg(M1 + c) + wx1 * __ldg(M1 + c + 1);
        float val = wy0 * a + wy1 * b;
        v[k] = p ? val : 0.0f;
    }

    float4* dst = (float4*)(out + (size_t)n * (IMG_H * IMG_W) + y * IMG_W + x);
    *dst = make_float4(v[0], v[1], v[2], v[3]);
}

// ---------------------------------------------------------------------------
// Static side stream + fork/join events (module init; not device allocations).
// ---------------------------------------------------------------------------
struct HxRes {
    cudaStream_t side;
    cudaEvent_t fork, join;
    HxRes() {
        cudaStreamCreateWithFlags(&side, cudaStreamNonBlocking);
        cudaEventCreateWithFlags(&fork, cudaEventDisableTiming);
        cudaEventCreateWithFlags(&join, cudaEventDisableTiming);
    }
};
static HxRes hx;

extern "C" void kernel_launch(void* const* d_in, const int* in_sizes, int n_in,
                              void* d_out, int out_size) {
    const float* bases = (const float*)d_in[0];
    const float* bf = (const float*)d_in[1];
    int n_roi = in_sizes[1] / BF_STRIDE;
    if (n_roi > N_MAX) n_roi = N_MAX;

    // Fork: masks on side stream, overlapped with the memset on main stream.
    cudaEventRecord(hx.fork, 0);
    cudaStreamWaitEvent(hx.side, hx.fork, 0);

    dim3 mgrid(n_roi, 7);
    masks_kernel<<<mgrid, 256, 0, hx.side>>>(bases, bf);
    cudaEventRecord(hx.join, hx.side);

    cudaMemsetAsync(d_out, 0, (size_t)out_size * sizeof(float));

    cudaStreamWaitEvent(0, hx.join, 0);
    dim3 pblock(32, 8);
    dim3 pgrid(XT, YT, n_roi);
    paste_box_kernel<<<pgrid, pblock>>>(bf, (float*)d_out);
}

// round 8
// speedup vs baseline: 1.1073x; 1.0439x over previous
#include <cuda_runtime.h>

#define N_MAX 128
#define BB 4
#define BH 136
#define BW 200
#define OUT 56
#define CO 14
#define IMG_H 544
#define IMG_W 800
#define BF_STRIDE (1 + 4 + BB * CO * CO) /* 789 */

#define XT 3    /* x tiles of 128 px (384 >= max box w 320 + slack) */
#define YT 8    /* y tiles of 32 rows (256 >= max box h 217.6 + slack) */

// Padded mask storage: per ROI 58 rows x 64 pitch, data at [1..56][1..56],
// zero border at row/col 0 and 57; cols 58..63 never written (stay 0 from
// .bss zero-init). ~1.9 MB.
#define MROWS 58
#define MPITCH 64
__device__ float g_mpad[N_MAX * MROWS * MPITCH];

// ---------------------------------------------------------------------------
// Kernel 1: fused roi_align + coeff bilinear upsample + softmax + sigmoid,
// writing into the padded layout. Chunk 0 also zeroes the border.
// Grid (n_roi, 7), block 256.
// ---------------------------------------------------------------------------
__global__ void masks_kernel(const float* __restrict__ bases,
                             const float* __restrict__ bf) {
    int n = blockIdx.x;
    int chunk = blockIdx.y;                  // 0..6, 8 mask rows each
    const float* row = bf + (size_t)n * BF_STRIDE;
    float* mp = g_mpad + (size_t)n * MROWS * MPITCH;

    // Zero border (rows 0 & 57 full width, cols 0 & 57 of rows 1..56).
    if (chunk == 0) {
        int t = threadIdx.x;
        if (t < MROWS) {
            mp[t] = 0.0f;                     // row 0
            mp[57 * MPITCH + t] = 0.0f;       // row 57
        } else if (t < MROWS + 112) {
            int k = t - MROWS;                // 0..111
            int r = 1 + (k >> 1);             // 1..56
            int c = (k & 1) ? 57 : 0;
            mp[r * MPITCH + c] = 0.0f;
        }
    }

    __shared__ float s_top[BB * CO * CO];
    for (int i = threadIdx.x; i < BB * CO * CO; i += blockDim.x)
        s_top[i] = row[5 + i];
    __syncthreads();

    int bidx = (int)row[0];
    float bx0 = row[1], by0 = row[2], bx1 = row[3], by1 = row[4];
    const float* feat = bases + (size_t)bidx * (BB * BH * BW);

    float sx0 = bx0 * 0.25f - 0.5f;
    float sy0 = by0 * 0.25f - 0.5f;
    float sx1 = bx1 * 0.25f - 0.5f;
    float sy1 = by1 * 0.25f - 0.5f;
    float bwd = (sx1 - sx0) * (1.0f / OUT);
    float bhd = (sy1 - sy0) * (1.0f / OUT);

    int p0 = chunk * 448;
    for (int t = threadIdx.x; t < 448; t += blockDim.x) {
        int p = p0 + t;
        int i = p / OUT;
        int j = p - i * OUT;

        float ys = sy0 + (i + 0.5f) * bhd;
        float xs = sx0 + (j + 0.5f) * bwd;
        bool valid = (ys >= -1.0f) && (ys <= (float)BH) &&
                     (xs >= -1.0f) && (xs <= (float)BW);
        float yc = fminf(fmaxf(ys, 0.0f), (float)(BH - 1));
        float xc = fminf(fmaxf(xs, 0.0f), (float)(BW - 1));
        int yl = min((int)yc, BH - 2);
        int xl = min((int)xc, BW - 2);
        float ly = yc - (float)yl, hy = 1.0f - ly;
        float lx = xc - (float)xl, hx = 1.0f - lx;

        float cy = fminf(fmaxf((i + 0.5f) * 0.25f - 0.5f, 0.0f), (float)(CO - 1));
        float cx = fminf(fmaxf((j + 0.5f) * 0.25f - 0.5f, 0.0f), (float)(CO - 1));
        int cyl = min((int)cy, CO - 2);
        int cxl = min((int)cx, CO - 2);
        float ty = cy - (float)cyl, sy = 1.0f - ty;
        float tx = cx - (float)cxl, sx = 1.0f - tx;

        float roi[BB], cf[BB];
#pragma unroll
        for (int b = 0; b < BB; b++) {
            const float* f = feat + b * BH * BW + yl * BW + xl;
            float fll = __ldg(f);
            float flh = __ldg(f + 1);
            float fhl = __ldg(f + BW);
            float fhh = __ldg(f + BW + 1);
            float v = hy * (hx * fll + lx * flh) + ly * (hx * fhl + lx * fhh);
            roi[b] = valid ? v : 0.0f;

            const float* tp = s_top + b * CO * CO + cyl * CO + cxl;
            cf[b] = sy * (sx * tp[0] + tx * tp[1]) + ty * (sx * tp[CO] + tx * tp[CO + 1]);
        }

        float m = fmaxf(fmaxf(cf[0], cf[1]), fmaxf(cf[2], cf[3]));
        float e0 = __expf(cf[0] - m), e1 = __expf(cf[1] - m);
        float e2 = __expf(cf[2] - m), e3 = __expf(cf[3] - m);
        float inv = 1.0f / (e0 + e1 + e2 + e3);
        float dot = (roi[0] * e0 + roi[1] * e1 + roi[2] * e2 + roi[3] * e3) * inv;
        mp[(i + 1) * MPITCH + (j + 1)] = 1.0f / (1.0f + __expf(-dot));
    }
}

// ---------------------------------------------------------------------------
// Kernel 2: paste. Each thread owns a 4x4 pixel patch: the x-interp LUT
// (tap index + masked weights) is computed once in registers and reused for
// 4 consecutive rows. Padded mask => no clamps on taps. Out-of-box threads
// exit before the row loop; invalid rows skip the store (memset covers them).
// Grid (XT, YT, n_roi), block (32, 8): tile = 128 px x 32 rows.
// ---------------------------------------------------------------------------
__global__ void __launch_bounds__(256)
paste_box_kernel(const float* __restrict__ bf, float* __restrict__ out) {
    int n = blockIdx.z;
    const float* row = bf + (size_t)n * BF_STRIDE;
    float x0 = __ldg(row + 1), y0 = __ldg(row + 2);
    float x1 = __ldg(row + 3), y1 = __ldg(row + 4);

    int xs = max(0, ((int)floorf(x0) - 4)) & ~3;
    int ysr = max(0, (int)floorf(y0) - 4);

    int x = xs + (blockIdx.x * 32 + threadIdx.x) * 4;
    if (x + 3 >= IMG_W) return;

    float inv_w = __fdividef((float)OUT, x1 - x0);
    float fxs = ((float)x + 0.5f - x0) * inv_w - 0.5f;
    if (fxs + 3.0f * inv_w <= -1.0f || fxs >= (float)OUT) return;

    // x LUT (registers), reused across the 4 rows.
    int c[4];
    float w0[4], w1[4];
#pragma unroll
    for (int k = 0; k < 4; k++) {
        float fx = fxs + (float)k * inv_w;
        bool valid = (fx > -1.0f) && (fx < (float)OUT);
        float fmx = floorf(fx);
        float wx1 = fx - fmx, wx0 = 1.0f - wx1;
        c[k] = min(max((int)fmx, -1), 61) + 1;   // 0..62, taps stay in pitch
        w0[k] = valid ? wx0 : 0.0f;
        w1[k] = valid ? wx1 : 0.0f;
    }

    float inv_h = __fdividef((float)OUT, y1 - y0);
    int ybase = ysr + blockIdx.y * 32 + threadIdx.y * 4;
    const float* Mb = g_mpad + (size_t)n * MROWS * MPITCH;
    float* orow = out + (size_t)n * (IMG_H * IMG_W) + (size_t)ybase * IMG_W + x;

#pragma unroll
    for (int r = 0; r < 4; r++, orow += IMG_W) {
        int y = ybase + r;
        if (y >= IMG_H) break;
        float fy = ((float)y + 0.5f - y0) * inv_h - 0.5f;
        if (fy <= -1.0f || fy >= (float)OUT) continue;

        float fmy = floorf(fy);
        float wy1 = fy - fmy, wy0 = 1.0f - wy1;
        const float* M0 = Mb + ((int)fmy + 1) * MPITCH;
        const float* M1 = M0 + MPITCH;

        float v[4];
#pragma unroll
        for (int k = 0; k < 4; k++) {
            float a = w0[k] * __ldg(M0 + c[k]) + w1[k] * __ldg(M0 + c[k] + 1);
            float b = w0[k] * __ldg(M1 + c[k]) + w1[k] * __ldg(M1 + c[k] + 1);
            v[k] = wy0 * a + wy1 * b;
        }
        *(float4*)orow = make_float4(v[0], v[1], v[2], v[3]);
    }
}

extern "C" void kernel_launch(void* const* d_in, const int* in_sizes, int n_in,
                              void* d_out, int out_size) {
    const float* bases = (const float*)d_in[0];
    const float* bf = (const float*)d_in[1];
    int n_roi = in_sizes[1] / BF_STRIDE;
    if (n_roi > N_MAX) n_roi = N_MAX;

    // Bulk zero-fill at memset-node bandwidth (serial: graph branches gave
    // no net overlap in R5/R7).
    cudaMemsetAsync(d_out, 0, (size_t)out_size * sizeof(float));

    dim3 mgrid(n_roi, 7);
    masks_kernel<<<mgrid, 256>>>(bases, bf);

    dim3 pblock(32, 8);
    dim3 pgrid(XT, YT, n_roi);
    paste_box_kernel<<<pgrid, pblock>>>(bf, (float*)d_out);
}